// round 11
// baseline (speedup 1.0000x reference)
#include <cuda_runtime.h>
#include <cuda_bf16.h>
#include <math.h>
#include <stdint.h>

#define HWN   16384
#define CC    256
#define BATCH 4
#define CHW   (CC*HWN)
#define GS    10        // gram split-K

// ---------------- scratch (static __device__, no allocations) ----------------
__device__ __align__(16) float d_Sx[BATCH*CC];
__device__ __align__(16) float d_Sxx[BATCH*CC];
__device__ __align__(16) float d_m[BATCH*CC];
__device__ __align__(16) float d_a[BATCH*CC];
__device__ __align__(16) float d_wa[BATCH*CC];
__device__ __align__(16) float d_rp[BATCH*CC];
__device__ __align__(16) float d_Wq[CC*CC];
__device__ __align__(16) float d_Wk[CC*CC];
__device__ __align__(16) float d_Wv[CC*CC];
__device__ __align__(16) float d_btq[CC];
__device__ __align__(16) float d_btk[CC];
__device__ __align__(16) float d_btv[CC];
__device__ __align__(16) __nv_bfloat16 d_b1[BATCH*CHW];   // 32 MB
__device__ __align__(16) __nv_bfloat16 d_b2[BATCH*CHW];   // 32 MB
__device__ __align__(16) float d_Gp[7*GS*BATCH*128*128];  // per-split tile partials
__device__ __align__(16) float d_G[BATCH*CC*CC];
__device__ __align__(16) float d_sc[BATCH*64*16];
__device__ __align__(16) float d_T[BATCH*CC*CC];
__device__ __align__(16) __nv_bfloat16 d_F1[BATCH*CC*CC];
__device__ __align__(16) float d_g[BATCH*CC];

// ---------------- mma / ldmatrix / cp.async helpers (baseline PTX, sm_80+) ----------------
__device__ __forceinline__ uint32_t smem_u32(const void* p) {
    uint32_t a;
    asm("{ .reg .u64 t; cvta.to.shared.u64 t, %1; cvt.u32.u64 %0, t; }" : "=r"(a) : "l"(p));
    return a;
}
__device__ __forceinline__ void ldm_x4(uint32_t* r, uint32_t addr) {
    asm volatile("ldmatrix.sync.aligned.m8n8.x4.shared.b16 {%0,%1,%2,%3}, [%4];"
                 : "=r"(r[0]), "=r"(r[1]), "=r"(r[2]), "=r"(r[3]) : "r"(addr));
}
__device__ __forceinline__ void ldm_x4_t(uint32_t* r, uint32_t addr) {
    asm volatile("ldmatrix.sync.aligned.m8n8.x4.trans.shared.b16 {%0,%1,%2,%3}, [%4];"
                 : "=r"(r[0]), "=r"(r[1]), "=r"(r[2]), "=r"(r[3]) : "r"(addr));
}
__device__ __forceinline__ void mma_bf16(float* c, const uint32_t* a,
                                         uint32_t b0, uint32_t b1) {
    asm volatile("mma.sync.aligned.m16n8k16.row.col.f32.bf16.bf16.f32 "
                 "{%0,%1,%2,%3}, {%4,%5,%6,%7}, {%8,%9}, {%0,%1,%2,%3};"
                 : "+f"(c[0]), "+f"(c[1]), "+f"(c[2]), "+f"(c[3])
                 : "r"(a[0]), "r"(a[1]), "r"(a[2]), "r"(a[3]), "r"(b0), "r"(b1));
}
__device__ __forceinline__ void cp16(uint32_t dst, const void* src) {
    asm volatile("cp.async.cg.shared.global [%0], [%1], 16;" :: "r"(dst), "l"(src) : "memory");
}
#define CP_COMMIT()  asm volatile("cp.async.commit_group;" ::: "memory")
#define CP_WAIT_2()  asm volatile("cp.async.wait_group 2;" ::: "memory")
#define CP_WAIT_1()  asm volatile("cp.async.wait_group 1;" ::: "memory")
#define CP_WAIT_0()  asm volatile("cp.async.wait_group 0;" ::: "memory")

#define SWA(o) ((o) ^ (((o) >> 3) & 0x70))
#define SWB(o) ((o) ^ ((((o) >> 8) & 7) << 4))

// ---------------- 1) fused convert + stats (blocks 0-1023) + pack (blocks 1024-1026) ----------------
__global__ void convpack_kernel(const float* __restrict__ x,
                                const float* __restrict__ qkvw,
                                const float* __restrict__ qkvb,
                                const float* __restrict__ gnb) {
    if (blockIdx.x < 1024) {
        int bc = blockIdx.x;
        const float4* p = (const float4*)(x + (size_t)bc * HWN);
        uint2* o1 = (uint2*)(d_b1 + (size_t)bc * HWN);
        uint2* o2 = (uint2*)(d_b2 + (size_t)bc * HWN);
        float s = 0.f, s2 = 0.f;
        for (int i = threadIdx.x; i < HWN/4; i += 256) {
            float4 v = p[i];
            float in[4] = {v.x, v.y, v.z, v.w};
            uint32_t hh[4], ll[4];
#pragma unroll
            for (int j = 0; j < 4; j++) {
                s  += in[j];
                s2 += in[j] * in[j];
                __nv_bfloat16 h = __float2bfloat16(in[j]);
                float hf = __bfloat162float(h);
                __nv_bfloat16 lo = __float2bfloat16(in[j] - hf);
                hh[j] = (uint32_t)__bfloat16_as_ushort(h);
                ll[j] = (uint32_t)__bfloat16_as_ushort(lo);
            }
            uint2 ph; ph.x = hh[0] | (hh[1] << 16); ph.y = hh[2] | (hh[3] << 16);
            uint2 pl; pl.x = ll[0] | (ll[1] << 16); pl.y = ll[2] | (ll[3] << 16);
            o1[i] = ph; o2[i] = pl;
        }
        for (int o = 16; o; o >>= 1) {
            s  += __shfl_down_sync(0xffffffffu, s, o);
            s2 += __shfl_down_sync(0xffffffffu, s2, o);
        }
        __shared__ float sh[8][2];
        int w = threadIdx.x >> 5, l = threadIdx.x & 31;
        if (l == 0) { sh[w][0] = s; sh[w][1] = s2; }
        __syncthreads();
        if (threadIdx.x == 0) {
            float S = 0.f, S2 = 0.f;
            for (int i = 0; i < 8; i++) { S += sh[i][0]; S2 += sh[i][1]; }
            d_Sx[bc] = S; d_Sxx[bc] = S2;
        }
    } else {
        int rid = (blockIdx.x - 1024) * 256 + threadIdx.x;   // 0..767
        if (rid >= 768) return;
        int sel = rid / 256;
        int p   = rid % 256;
        int h = p >> 2, dd = p & 3;
        int src = h * 12 + sel * 4 + dd;
        const float* wrow = qkvw + src * 256;
        float* dst = (sel == 0 ? d_Wq : (sel == 1 ? d_Wk : d_Wv)) + p * 256;
        float dot = 0.f;
        for (int c = 0; c < 256; c++) {
            float w = wrow[c];
            dst[c] = w;
            dot += w * gnb[c];
        }
        float bt = qkvb[src] + dot;
        if (sel == 0) d_btq[p] = bt; else if (sel == 1) d_btk[p] = bt; else d_btv[p] = bt;
    }
}

// ---------------- 2) HMMA Gram tiles (jid 0-6) + groupstats (jid 7) ----------------
// jid 0..2: P = b1_i b1_j^T, (ti,tj) in {(0,0),(0,1),(1,1)}
// jid 3..6: M = b1_i b2_j^T, (ti,tj) = ((jid-3)>>1, (jid-3)&1)
// jid 7 (split 0, b 0 only): group stats -> m, a, wa, rp (consumed by NEXT kernel)
__global__ void __launch_bounds__(256, 2) gram_mma_kernel(const float* __restrict__ gnw) {
    extern __shared__ char sm[];
    int b = blockIdx.z, split = blockIdx.y, jid = blockIdx.x;
    if (jid == 7) {
        if (split != 0 || b != 0) return;
        int t = threadIdx.x;
        if (t >= 128) return;
        int bb = t >> 5, g = t & 31;
        float s = 0.f, s2 = 0.f;
        for (int c8 = 0; c8 < 8; c8++) {
            int idx = bb * 256 + g * 8 + c8;
            s += d_Sx[idx]; s2 += d_Sxx[idx];
        }
        const float n = 8.f * (float)HWN;
        float mean = s / n;
        float var  = (s2 - n * mean * mean) / (n - 1.f);
        float a = rsqrtf(var + 1e-5f);
        for (int c8 = 0; c8 < 8; c8++) {
            int c = g * 8 + c8;
            int idx = bb * 256 + c;
            d_m[idx] = mean;
            d_a[idx] = a;
            float wa = gnw[c] * a;
            d_wa[idx] = wa;
            d_rp[idx] = wa * (d_Sx[idx] - (float)HWN * mean);
        }
        return;
    }
    int ti, tj;
    const __nv_bfloat16* Bbase;
    if (jid < 3) { ti = (jid == 2) ? 1 : 0; tj = (jid == 0) ? 0 : 1; Bbase = d_b1; }
    else { int j2 = jid - 3; ti = j2 >> 1; tj = j2 & 1; Bbase = d_b2; }
    int nch = 25 + (split < 6 ? 1 : 0);
    int ch0 = split * 25 + (split < 6 ? split : 6);
    int tid = threadIdx.x, wid = tid >> 5, l = tid & 31;
    int wr = wid >> 2, wc = wid & 3;
    uint32_t sb = smem_u32(sm);

    const __nv_bfloat16* Ap = d_b1  + (size_t)b * CHW + (size_t)(ti * 128) * HWN;
    const __nv_bfloat16* Bp = Bbase + (size_t)b * CHW + (size_t)(tj * 128) * HWN;

    float acc[4][4][4] = {};
    int frag_row = ((l >> 3) & 1) * 8 + (l & 7);
    int koff = (l >> 4) * 8;

    auto issue = [&](int ch, int st) {
        int k0 = (ch0 + ch) * 64;
#pragma unroll
        for (int it = 0; it < 8; it++) {
            int s = tid + it * 256;          // 0..2047
            int buf = s >> 10;
            int r = (s >> 3) & 127;
            int c = s & 7;
            const __nv_bfloat16* src = buf ? Bp : Ap;
            uint32_t dst = sb + st * 32768 + buf * 16384
                         + SWA((uint32_t)(r * 128 + c * 16));
            cp16(dst, src + (size_t)r * HWN + k0 + c * 8);
        }
        CP_COMMIT();
    };

    issue(0, 0);
    issue(1, 1);
    for (int ch = 0; ch < nch; ch++) {
        int st = ch % 3;
        if (ch + 2 < nch)      { issue(ch + 2, (ch + 2) % 3); CP_WAIT_2(); }
        else if (ch + 1 < nch) { CP_WAIT_1(); }
        else                   { CP_WAIT_0(); }
        __syncthreads();
        uint32_t stb = sb + st * 32768;
#pragma unroll
        for (int ks = 0; ks < 4; ks++) {
            int kb = (ks * 16 + koff) * 2;
            uint32_t a[4][4], bf[2][4];
#pragma unroll
            for (int g = 0; g < 2; g++) {
                uint32_t off = (uint32_t)((wc * 32 + g * 16 + frag_row) * 128 + kb);
                ldm_x4(bf[g], stb + 16384 + SWA(off));
            }
#pragma unroll
            for (int mt = 0; mt < 4; mt++) {
                uint32_t off = (uint32_t)((wr * 64 + mt * 16 + frag_row) * 128 + kb);
                ldm_x4(a[mt], stb + SWA(off));
            }
#pragma unroll
            for (int mt = 0; mt < 4; mt++)
#pragma unroll
                for (int nt = 0; nt < 4; nt++) {
                    int g = nt >> 1, p = nt & 1;
                    mma_bf16(acc[mt][nt], a[mt], bf[g][p], bf[g][p + 2]);
                }
        }
        __syncthreads();
    }
    float* gp = d_Gp + ((size_t)((jid * GS + split) * BATCH + b)) * 16384;
#pragma unroll
    for (int mt = 0; mt < 4; mt++)
#pragma unroll
        for (int nt = 0; nt < 4; nt++) {
            int row = wr * 64 + mt * 16 + (l >> 2);
            int col = wc * 32 + nt * 8 + (l & 3) * 2;
            float2 v0; v0.x = acc[mt][nt][0]; v0.y = acc[mt][nt][1];
            float2 v1; v1.x = acc[mt][nt][2]; v1.y = acc[mt][nt][3];
            *(float2*)&gp[row * 128 + col] = v0;
            *(float2*)&gp[(row + 8) * 128 + col] = v1;
        }
}

// ---------------- 3) combine: split-sum of P + M + M^T + GN corrections -> G' ----------------
__global__ void combineG_kernel() {
    int idx = blockIdx.x * 256 + threadIdx.x;   // < 4*65536
    int b = idx >> 16;
    int ij = idx & 65535;
    int i = ij >> 8, j = ij & 255;
    int hi = i >> 7, hj = j >> 7, il = i & 127, jl = j & 127;
    int pj = hi + hj;                            // P job: 0,1,2
    int pe = (hi <= hj) ? (il * 128 + jl) : (jl * 128 + il);
    size_t bP  = ((size_t)(pj * GS) * BATCH + b) * 16384 + pe;
    size_t bM1 = ((size_t)((3 + hi * 2 + hj) * GS) * BATCH + b) * 16384 + il * 128 + jl;
    size_t bM2 = ((size_t)((3 + hj * 2 + hi) * GS) * BATCH + b) * 16384 + jl * 128 + il;
    const size_t ss = (size_t)BATCH * 16384;
    float sum = 0.f;
#pragma unroll
    for (int sp = 0; sp < GS; sp++)
        sum += d_Gp[bP + sp * ss] + d_Gp[bM1 + sp * ss] + d_Gp[bM2 + sp * ss];
    int bi = b * 256 + i, bj = b * 256 + j;
    float g = d_wa[bi] * d_wa[bj] *
              (sum - d_m[bi] * d_Sx[bj] - d_m[bj] * d_Sx[bi] + (float)HWN * d_m[bi] * d_m[bj]);
    d_G[idx] = g;
}

// ---------------- 4) per-head scores: 4x4 block-diag of Wq G' Wk^T + corrections ----------------
__global__ void headscores_kernel() {
    int h = blockIdx.x, b = blockIdx.y;
    int tid = threadIdx.x;                        // 256
    __shared__ float wq_s[1024], wk_s[1024];
    __shared__ float red[8][24], fin[24];
    for (int i = tid; i < 1024; i += 256) {
        wq_s[i] = d_Wq[h * 1024 + i];
        wk_s[i] = d_Wk[h * 1024 + i];
    }
    __syncthreads();
    int c = tid;
    float v1[4] = {};
    const float* Gb = d_G + b * 65536;
    for (int p = 0; p < 256; p++) {
        float g = Gb[p * 256 + c];
        v1[0] += wq_s[p] * g;
        v1[1] += wq_s[256 + p] * g;
        v1[2] += wq_s[512 + p] * g;
        v1[3] += wq_s[768 + p] * g;
    }
    float rp = d_rp[b * 256 + c];
    float part[24];
#pragma unroll
    for (int d = 0; d < 4; d++)
#pragma unroll
        for (int e = 0; e < 4; e++)
            part[d * 4 + e] = v1[d] * wk_s[e * 256 + c];
#pragma unroll
    for (int d = 0; d < 4; d++) part[16 + d] = wq_s[d * 256 + c] * rp;
#pragma unroll
    for (int e = 0; e < 4; e++) part[20 + e] = wk_s[e * 256 + c] * rp;
#pragma unroll
    for (int k = 0; k < 24; k++)
        for (int o = 16; o; o >>= 1)
            part[k] += __shfl_down_sync(0xffffffffu, part[k], o);
    int wd = tid >> 5, ln = tid & 31;
    if (ln == 0)
#pragma unroll
        for (int k = 0; k < 24; k++) red[wd][k] = part[k];
    __syncthreads();
    if (tid < 24) {
        float s = 0.f;
        for (int w = 0; w < 8; w++) s += red[w][tid];
        fin[tid] = s;
    }
    __syncthreads();
    if (tid < 16) {
        int d = tid >> 2, e = tid & 3;
        float s = fin[tid]
                + fin[16 + d] * d_btk[h * 4 + e]
                + d_btq[h * 4 + d] * fin[20 + e]
                + (float)HWN * d_btq[h * 4 + d] * d_btk[h * 4 + e];
        d_sc[(b * 64 + h) * 16 + tid] = 0.5f * s;
    }
}

// ---------------- 5) softmax + T + u + g base ----------------
__global__ void softmax_t_kernel(const float* __restrict__ gnw,
                                 const float* __restrict__ outw,
                                 const float* __restrict__ outb) {
    int b = blockIdx.x;
    int tid = threadIdx.x;                 // 512
    __shared__ float Ssh[64][16];
    __shared__ float amsh[256], tvsh[256], ush[256], tmush[256];
    {
        int w = tid >> 5;                  // pair 0..15
        int l = tid & 31;
        float v0 = d_sc[((b * 64 + l) << 4) + w];
        float v1 = d_sc[((b * 64 + l + 32) << 4) + w];
        float mx = fmaxf(v0, v1);
        for (int o = 16; o; o >>= 1) mx = fmaxf(mx, __shfl_xor_sync(0xffffffffu, mx, o));
        float e0 = expf(v0 - mx), e1 = expf(v1 - mx);
        float s = e0 + e1;
        for (int o = 16; o; o >>= 1) s += __shfl_xor_sync(0xffffffffu, s, o);
        Ssh[l][w] = e0 / s;
        Ssh[l + 32][w] = e1 / s;
    }
    if (tid < 256) amsh[tid] = d_a[b * 256 + tid] * d_m[b * 256 + tid];
    __syncthreads();
    for (int e = tid; e < 65536; e += 512) {
        int p = e >> 8, c = e & 255;
        int h = p >> 2, dd = p & 3;
        const float* S = &Ssh[h][dd * 4];
        float s = S[0] * d_Wv[(h*4+0)*256 + c] + S[1] * d_Wv[(h*4+1)*256 + c]
                + S[2] * d_Wv[(h*4+2)*256 + c] + S[3] * d_Wv[(h*4+3)*256 + c];
        d_T[((size_t)b * 256 + p) * 256 + c] = gnw[c] * s;
    }
    if (tid < 256) {
        int h = tid >> 2, dd = tid & 3;
        float tv = 0.f;
        for (int e2 = 0; e2 < 4; e2++) tv += Ssh[h][dd * 4 + e2] * d_btv[h * 4 + e2];
        tvsh[tid] = tv;
    }
    __syncthreads();
    {
        int p = tid >> 1, half = tid & 1;
        const float* Trow = d_T + ((size_t)b * 256 + p) * 256 + half * 128;
        const float* am = amsh + half * 128;
        float u = 0.f;
        for (int c = 0; c < 128; c++) u += Trow[c] * am[c];
        u += __shfl_down_sync(0xffffffffu, u, 1);
        if (!half) ush[p] = u;
    }
    __syncthreads();
    if (tid < 256) tmush[tid] = tvsh[tid] - ush[tid];
    __syncthreads();
    if (tid < 256) {
        float g = outb[tid];
        const float* ow = outw + tid * 256;
        for (int p = 0; p < 256; p++) g += ow[p] * tmush[p];
        d_g[b * 256 + tid] = g;
    }
}

// ---------------- 6) E-GEMM: F1 = bf16( (out_w @ T) * diag(a) ) ----------------
__global__ void egemm_kernel(const float* __restrict__ outw) {
    int b = blockIdx.z;
    const float* A = outw;
    const float* B = d_T + b * 65536;

    __shared__ float As[16][64];
    __shared__ float Bs[16][64];
    int m0 = blockIdx.x * 64, n0 = blockIdx.y * 64;
    int tid = threadIdx.x;
    int tx = tid & 15, ty = tid >> 4;
    int ar = tid >> 2, asg = tid & 3;
    int br = tid >> 4, bc = tid & 15;
    float acc[4][4] = {};
    for (int k0 = 0; k0 < 256; k0 += 16) {
        float4 av = *(const float4*)&A[(m0 + ar) * 256 + k0 + asg * 4];
        As[asg*4+0][ar] = av.x; As[asg*4+1][ar] = av.y; As[asg*4+2][ar] = av.z; As[asg*4+3][ar] = av.w;
        float4 bv = *(const float4*)&B[(k0 + br) * 256 + n0 + bc * 4];
        *(float4*)&Bs[br][bc * 4] = bv;
        __syncthreads();
#pragma unroll
        for (int kk = 0; kk < 16; kk++) {
            float4 a4 = *(const float4*)&As[kk][ty * 4];
            float4 b4 = *(const float4*)&Bs[kk][tx * 4];
            float avv[4] = {a4.x, a4.y, a4.z, a4.w};
            float bvv[4] = {b4.x, b4.y, b4.z, b4.w};
#pragma unroll
            for (int i = 0; i < 4; i++)
#pragma unroll
                for (int j = 0; j < 4; j++)
                    acc[i][j] += avv[i] * bvv[j];
        }
        __syncthreads();
    }
    int colb = n0 + tx * 4;
    float a0 = d_a[b * 256 + colb + 0];
    float a1 = d_a[b * 256 + colb + 1];
    float a2 = d_a[b * 256 + colb + 2];
    float a3 = d_a[b * 256 + colb + 3];
#pragma unroll
    for (int i = 0; i < 4; i++) {
        int m = m0 + ty * 4 + i;
        uint32_t h0 = (uint32_t)__bfloat16_as_ushort(__float2bfloat16(acc[i][0] * a0));
        uint32_t h1 = (uint32_t)__bfloat16_as_ushort(__float2bfloat16(acc[i][1] * a1));
        uint32_t h2 = (uint32_t)__bfloat16_as_ushort(__float2bfloat16(acc[i][2] * a2));
        uint32_t h3 = (uint32_t)__bfloat16_as_ushort(__float2bfloat16(acc[i][3] * a3));
        uint2 v; v.x = h0 | (h1 << 16); v.y = h2 | (h3 << 16);
        *(uint2*)&d_F1[(size_t)(b * 256 + m) * 256 + colb] = v;
    }
}

// ---------------- 7) HMMA final GEMM, 3-stage: out = F@x + g + skip ----------------
__global__ void __launch_bounds__(256, 2) fgemm_kernel(const float* __restrict__ x,
                                                       float* __restrict__ out) {
    extern __shared__ char sm[];
    int b = blockIdx.z;
    int m0 = blockIdx.x * 128;
    int n0 = blockIdx.y * 128;
    int tid = threadIdx.x, wid = tid >> 5, l = tid & 31;
    int wr = wid >> 2, wc = wid & 3;
    uint32_t sb = smem_u32(sm);

    const __nv_bfloat16* A1 = d_F1 + b * 65536;
    const __nv_bfloat16* B1 = d_b1 + (size_t)b * CHW;

    float acc[4][4][4] = {};
    int frag_row = ((l >> 3) & 1) * 8 + (l & 7);
    int koff = (l >> 4) * 8;

    auto issue = [&](int ch, int st) {
        int k0 = ch * 64;
#pragma unroll
        for (int it = 0; it < 8; it++) {
            int s = tid + it * 256;          // 0..2047
            if (s < 1024) {                  // A
                int r = s >> 3;
                int c = s & 7;
                uint32_t dst = sb + st * 32768 + SWA((uint32_t)(r * 128 + c * 16));
                cp16(dst, A1 + (m0 + r) * 256 + k0 + c * 8);
            } else {                         // B
                int v2 = s & 1023;
                int kr = v2 >> 4;
                int c = v2 & 15;
                uint32_t dst = sb + st * 32768 + 16384 + SWB((uint32_t)(kr * 256 + c * 16));
                cp16(dst, B1 + (size_t)(k0 + kr) * HWN + n0 + c * 8);
            }
        }
        CP_COMMIT();
    };

    issue(0, 0);
    issue(1, 1);
    for (int ch = 0; ch < 4; ch++) {
        int st = ch % 3;
        if (ch + 2 < 4)      { issue(ch + 2, (ch + 2) % 3); CP_WAIT_2(); }
        else if (ch + 1 < 4) { CP_WAIT_1(); }
        else                 { CP_WAIT_0(); }
        __syncthreads();
        uint32_t stb = sb + st * 32768;
#pragma unroll
        for (int ks = 0; ks < 4; ks++) {
            int kb = (ks * 16 + koff) * 2;
            uint32_t a[4][4], bf[2][4];
#pragma unroll
            for (int g = 0; g < 2; g++) {
                uint32_t off = (uint32_t)((ks * 16 + frag_row) * 256
                                          + (wc * 32 + g * 16 + koff) * 2);
                ldm_x4_t(bf[g], stb + 16384 + SWB(off));
            }
#pragma unroll
            for (int mt = 0; mt < 4; mt++) {
                uint32_t off = (uint32_t)((wr * 64 + mt * 16 + frag_row) * 128 + kb);
                ldm_x4(a[mt], stb + SWA(off));
            }
#pragma unroll
            for (int mt = 0; mt < 4; mt++)
#pragma unroll
                for (int nt = 0; nt < 4; nt++) {
                    int g = nt >> 1, p = nt & 1;
                    mma_bf16(acc[mt][nt], a[mt], bf[g][p*2], bf[g][p*2+1]);
                }
        }
        __syncthreads();
    }
    const float* xb = x + (size_t)b * CHW;
    float* ob = out + (size_t)b * CHW;
#pragma unroll
    for (int mt = 0; mt < 4; mt++) {
        int row = m0 + wr * 64 + mt * 16 + (l >> 2);
        float g0 = d_g[b * 256 + row];
        float g1 = d_g[b * 256 + row + 8];
#pragma unroll
        for (int nt = 0; nt < 4; nt++) {
            int col = n0 + wc * 32 + nt * 8 + (l & 3) * 2;
            float2 s0 = *(const float2*)&xb[(size_t)row * HWN + col];
            float2 s1 = *(const float2*)&xb[(size_t)(row + 8) * HWN + col];
            float2 v0, v1;
            v0.x = acc[mt][nt][0] + g0 + s0.x;
            v0.y = acc[mt][nt][1] + g0 + s0.y;
            v1.x = acc[mt][nt][2] + g1 + s1.x;
            v1.y = acc[mt][nt][3] + g1 + s1.y;
            *(float2*)&ob[(size_t)row * HWN + col] = v0;
            *(float2*)&ob[(size_t)(row + 8) * HWN + col] = v1;
        }
    }
}

// ---------------- launch ----------------
extern "C" void kernel_launch(void* const* d_in, const int* in_sizes, int n_in,
                              void* d_out, int out_size) {
    const float* x    = (const float*)d_in[0];
    const float* gnw  = (const float*)d_in[1];
    const float* gnb  = (const float*)d_in[2];
    const float* qkvw = (const float*)d_in[3];
    const float* qkvb = (const float*)d_in[4];
    const float* outw = (const float*)d_in[5];
    const float* outb = (const float*)d_in[6];
    float* out = (float*)d_out;

    cudaFuncSetAttribute(gram_mma_kernel, cudaFuncAttributeMaxDynamicSharedMemorySize, 98304);
    cudaFuncSetAttribute(fgemm_kernel,    cudaFuncAttributeMaxDynamicSharedMemorySize, 98304);

    convpack_kernel<<<1027, 256>>>(x, qkvw, qkvb, gnb);
    gram_mma_kernel<<<dim3(8, GS, BATCH), 256, 98304>>>(gnw);
    combineG_kernel<<<1024, 256>>>();
    headscores_kernel<<<dim3(64, BATCH), 256>>>();
    softmax_t_kernel<<<BATCH, 512>>>(gnw, outw, outb);
    egemm_kernel<<<dim3(4, 4, BATCH), 256>>>(outw);
    fgemm_kernel<<<dim3(2, HWN / 128, BATCH), 256, 98304>>>(x, out);
}

// round 12
// speedup vs baseline: 1.1016x; 1.1016x over previous
#include <cuda_runtime.h>
#include <cuda_bf16.h>
#include <math.h>
#include <stdint.h>

#define HWN   16384
#define CC    256
#define BATCH 4
#define CHW   (CC*HWN)
#define GS    10        // gram split-K

// ---------------- scratch (static __device__, no allocations) ----------------
__device__ __align__(16) float d_Sx[BATCH*CC];
__device__ __align__(16) float d_Sxx[BATCH*CC];
__device__ __align__(16) float d_m[BATCH*CC];
__device__ __align__(16) float d_a[BATCH*CC];
__device__ __align__(16) float d_wa[BATCH*CC];
__device__ __align__(16) float d_rp[BATCH*CC];
__device__ __align__(16) float d_Wq[CC*CC];
__device__ __align__(16) float d_Wk[CC*CC];
__device__ __align__(16) float d_Wv[CC*CC];
__device__ __align__(16) float d_btq[CC];
__device__ __align__(16) float d_btk[CC];
__device__ __align__(16) float d_btv[CC];
__device__ __align__(16) __nv_bfloat16 d_b1[BATCH*CHW];   // 32 MB
__device__ __align__(16) __nv_bfloat16 d_b2[BATCH*CHW];   // 32 MB
__device__ __align__(16) float d_Gp[7*GS*BATCH*128*128];  // per-split tile partials
__device__ __align__(16) float d_Gs[7*BATCH*128*128];     // split-summed tiles
__device__ __align__(16) float d_G[BATCH*CC*CC];
__device__ __align__(16) float d_sc[BATCH*64*16];
__device__ __align__(16) float d_T[BATCH*CC*CC];
__device__ __align__(16) __nv_bfloat16 d_F1[BATCH*CC*CC];
__device__ __align__(16) float d_g[BATCH*CC];

// ---------------- mma / ldmatrix / cp.async helpers (baseline PTX, sm_80+) ----------------
__device__ __forceinline__ uint32_t smem_u32(const void* p) {
    uint32_t a;
    asm("{ .reg .u64 t; cvta.to.shared.u64 t, %1; cvt.u32.u64 %0, t; }" : "=r"(a) : "l"(p));
    return a;
}
__device__ __forceinline__ void ldm_x4(uint32_t* r, uint32_t addr) {
    asm volatile("ldmatrix.sync.aligned.m8n8.x4.shared.b16 {%0,%1,%2,%3}, [%4];"
                 : "=r"(r[0]), "=r"(r[1]), "=r"(r[2]), "=r"(r[3]) : "r"(addr));
}
__device__ __forceinline__ void ldm_x4_t(uint32_t* r, uint32_t addr) {
    asm volatile("ldmatrix.sync.aligned.m8n8.x4.trans.shared.b16 {%0,%1,%2,%3}, [%4];"
                 : "=r"(r[0]), "=r"(r[1]), "=r"(r[2]), "=r"(r[3]) : "r"(addr));
}
__device__ __forceinline__ void mma_bf16(float* c, const uint32_t* a,
                                         uint32_t b0, uint32_t b1) {
    asm volatile("mma.sync.aligned.m16n8k16.row.col.f32.bf16.bf16.f32 "
                 "{%0,%1,%2,%3}, {%4,%5,%6,%7}, {%8,%9}, {%0,%1,%2,%3};"
                 : "+f"(c[0]), "+f"(c[1]), "+f"(c[2]), "+f"(c[3])
                 : "r"(a[0]), "r"(a[1]), "r"(a[2]), "r"(a[3]), "r"(b0), "r"(b1));
}
__device__ __forceinline__ void cp16(uint32_t dst, const void* src) {
    asm volatile("cp.async.cg.shared.global [%0], [%1], 16;" :: "r"(dst), "l"(src) : "memory");
}
#define CP_COMMIT()  asm volatile("cp.async.commit_group;" ::: "memory")
#define CP_WAIT_2()  asm volatile("cp.async.wait_group 2;" ::: "memory")
#define CP_WAIT_1()  asm volatile("cp.async.wait_group 1;" ::: "memory")
#define CP_WAIT_0()  asm volatile("cp.async.wait_group 0;" ::: "memory")

#define SWA(o) ((o) ^ (((o) >> 3) & 0x70))
#define SWB(o) ((o) ^ ((((o) >> 8) & 7) << 4))

// ---------------- 1) fused convert + stats ----------------
__global__ void convstats_kernel(const float* __restrict__ x) {
    int bc = blockIdx.x;
    const float4* p = (const float4*)(x + (size_t)bc * HWN);
    uint2* o1 = (uint2*)(d_b1 + (size_t)bc * HWN);
    uint2* o2 = (uint2*)(d_b2 + (size_t)bc * HWN);
    float s = 0.f, s2 = 0.f;
    for (int i = threadIdx.x; i < HWN/4; i += 256) {
        float4 v = p[i];
        float in[4] = {v.x, v.y, v.z, v.w};
        uint32_t hh[4], ll[4];
#pragma unroll
        for (int j = 0; j < 4; j++) {
            s  += in[j];
            s2 += in[j] * in[j];
            __nv_bfloat16 h = __float2bfloat16(in[j]);
            float hf = __bfloat162float(h);
            __nv_bfloat16 lo = __float2bfloat16(in[j] - hf);
            hh[j] = (uint32_t)__bfloat16_as_ushort(h);
            ll[j] = (uint32_t)__bfloat16_as_ushort(lo);
        }
        uint2 ph; ph.x = hh[0] | (hh[1] << 16); ph.y = hh[2] | (hh[3] << 16);
        uint2 pl; pl.x = ll[0] | (ll[1] << 16); pl.y = ll[2] | (ll[3] << 16);
        o1[i] = ph; o2[i] = pl;
    }
    for (int o = 16; o; o >>= 1) {
        s  += __shfl_down_sync(0xffffffffu, s, o);
        s2 += __shfl_down_sync(0xffffffffu, s2, o);
    }
    __shared__ float sh[8][2];
    int w = threadIdx.x >> 5, l = threadIdx.x & 31;
    if (l == 0) { sh[w][0] = s; sh[w][1] = s2; }
    __syncthreads();
    if (threadIdx.x == 0) {
        float S = 0.f, S2 = 0.f;
        for (int i = 0; i < 8; i++) { S += sh[i][0]; S2 += sh[i][1]; }
        d_Sx[bc] = S; d_Sxx[bc] = S2;
    }
}

// ---------------- 2) prep = pack(blocks 0-5) + groupstats(block 6) ----------------
__global__ void prep_kernel(const float* __restrict__ qkvw,
                            const float* __restrict__ qkvb,
                            const float* __restrict__ gnb,
                            const float* __restrict__ gnw) {
    if (blockIdx.x < 6) {
        int rid = blockIdx.x * 128 + threadIdx.x;     // 0..767
        int sel = rid / 256;
        int p   = rid % 256;
        int h = p >> 2, dd = p & 3;
        int src = h * 12 + sel * 4 + dd;
        const float* wrow = qkvw + src * 256;
        float* dst = (sel == 0 ? d_Wq : (sel == 1 ? d_Wk : d_Wv)) + p * 256;
        float dot = 0.f;
        for (int c = 0; c < 256; c++) {
            float w = wrow[c];
            dst[c] = w;
            dot += w * gnb[c];
        }
        float bt = qkvb[src] + dot;
        if (sel == 0) d_btq[p] = bt; else if (sel == 1) d_btk[p] = bt; else d_btv[p] = bt;
    } else {
        int t = threadIdx.x;             // 0..127 = (b,g)
        int b = t >> 5, g = t & 31;
        float s = 0.f, s2 = 0.f;
        for (int c8 = 0; c8 < 8; c8++) {
            int idx = b * 256 + g * 8 + c8;
            s += d_Sx[idx]; s2 += d_Sxx[idx];
        }
        const float n = 8.f * (float)HWN;
        float mean = s / n;
        float var  = (s2 - n * mean * mean) / (n - 1.f);
        float a = rsqrtf(var + 1e-5f);
        for (int c8 = 0; c8 < 8; c8++) {
            int c = g * 8 + c8;
            int idx = b * 256 + c;
            d_m[idx] = mean;
            d_a[idx] = a;
            float wa = gnw[c] * a;
            d_wa[idx] = wa;
            d_rp[idx] = wa * (d_Sx[idx] - (float)HWN * mean);
        }
    }
}

// ---------------- 3) HMMA Gram tiles: 7 single-product jobs, 3-stage pipeline ----------------
// jid 0..2: P = b1_i b1_j^T, (ti,tj) in {(0,0),(0,1),(1,1)}
// jid 3..6: M = b1_i b2_j^T, (ti,tj) = ((jid-3)>>1, (jid-3)&1)
__global__ void __launch_bounds__(256, 2) gram_mma_kernel() {
    extern __shared__ char sm[];
    int b = blockIdx.z, split = blockIdx.y, jid = blockIdx.x;
    int ti, tj;
    const __nv_bfloat16* Bbase;
    if (jid < 3) { ti = (jid == 2) ? 1 : 0; tj = (jid == 0) ? 0 : 1; Bbase = d_b1; }
    else { int j2 = jid - 3; ti = j2 >> 1; tj = j2 & 1; Bbase = d_b2; }
    int nch = 25 + (split < 6 ? 1 : 0);
    int ch0 = split * 25 + (split < 6 ? split : 6);
    int tid = threadIdx.x, wid = tid >> 5, l = tid & 31;
    int wr = wid >> 2, wc = wid & 3;
    uint32_t sb = smem_u32(sm);

    const __nv_bfloat16* Ap = d_b1  + (size_t)b * CHW + (size_t)(ti * 128) * HWN;
    const __nv_bfloat16* Bp = Bbase + (size_t)b * CHW + (size_t)(tj * 128) * HWN;

    float acc[4][4][4] = {};
    int frag_row = ((l >> 3) & 1) * 8 + (l & 7);
    int koff = (l >> 4) * 8;

    auto issue = [&](int ch, int st) {
        int k0 = (ch0 + ch) * 64;
#pragma unroll
        for (int it = 0; it < 8; it++) {
            int s = tid + it * 256;          // 0..2047
            int buf = s >> 10;
            int r = (s >> 3) & 127;
            int c = s & 7;
            const __nv_bfloat16* src = buf ? Bp : Ap;
            uint32_t dst = sb + st * 32768 + buf * 16384
                         + SWA((uint32_t)(r * 128 + c * 16));
            cp16(dst, src + (size_t)r * HWN + k0 + c * 8);
        }
        CP_COMMIT();
    };

    issue(0, 0);
    issue(1, 1);
    for (int ch = 0; ch < nch; ch++) {
        int st = ch % 3;
        if (ch + 2 < nch)      { issue(ch + 2, (ch + 2) % 3); CP_WAIT_2(); }
        else if (ch + 1 < nch) { CP_WAIT_1(); }
        else                   { CP_WAIT_0(); }
        __syncthreads();
        uint32_t stb = sb + st * 32768;
#pragma unroll
        for (int ks = 0; ks < 4; ks++) {
            int kb = (ks * 16 + koff) * 2;
            uint32_t a[4][4], bf[2][4];
#pragma unroll
            for (int g = 0; g < 2; g++) {
                uint32_t off = (uint32_t)((wc * 32 + g * 16 + frag_row) * 128 + kb);
                ldm_x4(bf[g], stb + 16384 + SWA(off));
            }
#pragma unroll
            for (int mt = 0; mt < 4; mt++) {
                uint32_t off = (uint32_t)((wr * 64 + mt * 16 + frag_row) * 128 + kb);
                ldm_x4(a[mt], stb + SWA(off));
            }
#pragma unroll
            for (int mt = 0; mt < 4; mt++)
#pragma unroll
                for (int nt = 0; nt < 4; nt++) {
                    int g = nt >> 1, p = nt & 1;
                    mma_bf16(acc[mt][nt], a[mt], bf[g][p], bf[g][p + 2]);
                }
        }
        __syncthreads();
    }
    float* gp = d_Gp + ((size_t)((jid * GS + split) * BATCH + b)) * 16384;
#pragma unroll
    for (int mt = 0; mt < 4; mt++)
#pragma unroll
        for (int nt = 0; nt < 4; nt++) {
            int row = wr * 64 + mt * 16 + (l >> 2);
            int col = wc * 32 + nt * 8 + (l & 3) * 2;
            float2 v0; v0.x = acc[mt][nt][0]; v0.y = acc[mt][nt][1];
            float2 v1; v1.x = acc[mt][nt][2]; v1.y = acc[mt][nt][3];
            *(float2*)&gp[row * 128 + col] = v0;
            *(float2*)&gp[(row + 8) * 128 + col] = v1;
        }
}

// ---------------- 4) sum over splits (coalesced) ----------------
__global__ void sumG_kernel() {
    int o = blockIdx.x * 256 + threadIdx.x;     // < 7*4*16384 = 458752
    int j = o >> 16;                            // job
    int rb = o & 65535;                         // b*16384 + e
    size_t base = (size_t)j * GS * BATCH * 16384 + rb;
    float s = 0.f;
    for (int sp = 0; sp < GS; sp++) s += d_Gp[base + (size_t)sp * BATCH * 16384];
    d_Gs[o] = s;
}

// ---------------- 5) combine P + M + M^T + GN corrections -> G' ----------------
__global__ void combineG_kernel() {
    int idx = blockIdx.x * 256 + threadIdx.x;   // < 4*65536
    int b = idx >> 16;
    int ij = idx & 65535;
    int i = ij >> 8, j = ij & 255;
    int hi = i >> 7, hj = j >> 7, il = i & 127, jl = j & 127;
    int pj = hi + hj;                            // 0,1,2
    int pe = (hi <= hj) ? (il * 128 + jl) : (jl * 128 + il);
    float sum = d_Gs[(pj * 4 + b) * 16384 + pe]
              + d_Gs[((3 + hi * 2 + hj) * 4 + b) * 16384 + il * 128 + jl]
              + d_Gs[((3 + hj * 2 + hi) * 4 + b) * 16384 + jl * 128 + il];
    int bi = b * 256 + i, bj = b * 256 + j;
    float g = d_wa[bi] * d_wa[bj] *
              (sum - d_m[bi] * d_Sx[bj] - d_m[bj] * d_Sx[bi] + (float)HWN * d_m[bi] * d_m[bj]);
    d_G[idx] = g;
}

// ---------------- 6) per-head scores: 4x4 block-diag of Wq G' Wk^T + corrections ----------------
// FIX (R12): unroll the p-loop for MLP — was 1 exposed L2 latency per iteration (47.6us).
__global__ void headscores_kernel() {
    int h = blockIdx.x, b = blockIdx.y;
    int tid = threadIdx.x;                        // 256
    __shared__ float wq_s[1024], wk_s[1024];
    __shared__ float red[8][24], fin[24];
    for (int i = tid; i < 1024; i += 256) {
        wq_s[i] = d_Wq[h * 1024 + i];
        wk_s[i] = d_Wk[h * 1024 + i];
    }
    __syncthreads();
    int c = tid;
    float v1[4] = {};
    const float* Gb = d_G + b * 65536 + c;
#pragma unroll 16
    for (int p = 0; p < 256; p++) {
        float g = Gb[p * 256];
        v1[0] += wq_s[p] * g;
        v1[1] += wq_s[256 + p] * g;
        v1[2] += wq_s[512 + p] * g;
        v1[3] += wq_s[768 + p] * g;
    }
    float rp = d_rp[b * 256 + c];
    float part[24];
#pragma unroll
    for (int d = 0; d < 4; d++)
#pragma unroll
        for (int e = 0; e < 4; e++)
            part[d * 4 + e] = v1[d] * wk_s[e * 256 + c];
#pragma unroll
    for (int d = 0; d < 4; d++) part[16 + d] = wq_s[d * 256 + c] * rp;
#pragma unroll
    for (int e = 0; e < 4; e++) part[20 + e] = wk_s[e * 256 + c] * rp;
#pragma unroll
    for (int k = 0; k < 24; k++)
        for (int o = 16; o; o >>= 1)
            part[k] += __shfl_down_sync(0xffffffffu, part[k], o);
    int wd = tid >> 5, ln = tid & 31;
    if (ln == 0)
#pragma unroll
        for (int k = 0; k < 24; k++) red[wd][k] = part[k];
    __syncthreads();
    if (tid < 24) {
        float s = 0.f;
        for (int w = 0; w < 8; w++) s += red[w][tid];
        fin[tid] = s;
    }
    __syncthreads();
    if (tid < 16) {
        int d = tid >> 2, e = tid & 3;
        float s = fin[tid]
                + fin[16 + d] * d_btk[h * 4 + e]
                + d_btq[h * 4 + d] * fin[20 + e]
                + (float)HWN * d_btq[h * 4 + d] * d_btk[h * 4 + e];
        d_sc[(b * 64 + h) * 16 + tid] = 0.5f * s;
    }
}

// ---------------- 7) softmax + T + u + g base ----------------
__global__ void softmax_t_kernel(const float* __restrict__ gnw,
                                 const float* __restrict__ outw,
                                 const float* __restrict__ outb) {
    int b = blockIdx.x;
    int tid = threadIdx.x;                 // 512
    __shared__ float Ssh[64][16];
    __shared__ float amsh[256], tvsh[256], ush[256], tmush[256];
    {
        int w = tid >> 5;                  // pair 0..15
        int l = tid & 31;
        float v0 = d_sc[((b * 64 + l) << 4) + w];
        float v1 = d_sc[((b * 64 + l + 32) << 4) + w];
        float mx = fmaxf(v0, v1);
        for (int o = 16; o; o >>= 1) mx = fmaxf(mx, __shfl_xor_sync(0xffffffffu, mx, o));
        float e0 = expf(v0 - mx), e1 = expf(v1 - mx);
        float s = e0 + e1;
        for (int o = 16; o; o >>= 1) s += __shfl_xor_sync(0xffffffffu, s, o);
        Ssh[l][w] = e0 / s;
        Ssh[l + 32][w] = e1 / s;
    }
    if (tid < 256) amsh[tid] = d_a[b * 256 + tid] * d_m[b * 256 + tid];
    __syncthreads();
    for (int e = tid; e < 65536; e += 512) {
        int p = e >> 8, c = e & 255;
        int h = p >> 2, dd = p & 3;
        const float* S = &Ssh[h][dd * 4];
        float s = S[0] * d_Wv[(h*4+0)*256 + c] + S[1] * d_Wv[(h*4+1)*256 + c]
                + S[2] * d_Wv[(h*4+2)*256 + c] + S[3] * d_Wv[(h*4+3)*256 + c];
        d_T[((size_t)b * 256 + p) * 256 + c] = gnw[c] * s;
    }
    if (tid < 256) {
        int h = tid >> 2, dd = tid & 3;
        float tv = 0.f;
        for (int e2 = 0; e2 < 4; e2++) tv += Ssh[h][dd * 4 + e2] * d_btv[h * 4 + e2];
        tvsh[tid] = tv;
    }
    __syncthreads();
    {
        int p = tid >> 1, half = tid & 1;
        const float* Trow = d_T + ((size_t)b * 256 + p) * 256 + half * 128;
        const float* am = amsh + half * 128;
        float u = 0.f;
        for (int c = 0; c < 128; c++) u += Trow[c] * am[c];
        u += __shfl_down_sync(0xffffffffu, u, 1);
        if (!half) ush[p] = u;
    }
    __syncthreads();
    if (tid < 256) tmush[tid] = tvsh[tid] - ush[tid];
    __syncthreads();
    if (tid < 256) {
        float g = outb[tid];
        const float* ow = outw + tid * 256;
        for (int p = 0; p < 256; p++) g += ow[p] * tmush[p];
        d_g[b * 256 + tid] = g;
    }
}

// ---------------- 8) E-GEMM: F1 = bf16( (out_w @ T) * diag(a) ) ----------------
__global__ void egemm_kernel(const float* __restrict__ outw) {
    int b = blockIdx.z;
    const float* A = outw;
    const float* B = d_T + b * 65536;

    __shared__ float As[16][64];
    __shared__ float Bs[16][64];
    int m0 = blockIdx.x * 64, n0 = blockIdx.y * 64;
    int tid = threadIdx.x;
    int tx = tid & 15, ty = tid >> 4;
    int ar = tid >> 2, asg = tid & 3;
    int br = tid >> 4, bc = tid & 15;
    float acc[4][4] = {};
    for (int k0 = 0; k0 < 256; k0 += 16) {
        float4 av = *(const float4*)&A[(m0 + ar) * 256 + k0 + asg * 4];
        As[asg*4+0][ar] = av.x; As[asg*4+1][ar] = av.y; As[asg*4+2][ar] = av.z; As[asg*4+3][ar] = av.w;
        float4 bv = *(const float4*)&B[(k0 + br) * 256 + n0 + bc * 4];
        *(float4*)&Bs[br][bc * 4] = bv;
        __syncthreads();
#pragma unroll
        for (int kk = 0; kk < 16; kk++) {
            float4 a4 = *(const float4*)&As[kk][ty * 4];
            float4 b4 = *(const float4*)&Bs[kk][tx * 4];
            float avv[4] = {a4.x, a4.y, a4.z, a4.w};
            float bvv[4] = {b4.x, b4.y, b4.z, b4.w};
#pragma unroll
            for (int i = 0; i < 4; i++)
#pragma unroll
                for (int j = 0; j < 4; j++)
                    acc[i][j] += avv[i] * bvv[j];
        }
        __syncthreads();
    }
    int colb = n0 + tx * 4;
    float a0 = d_a[b * 256 + colb + 0];
    float a1 = d_a[b * 256 + colb + 1];
    float a2 = d_a[b * 256 + colb + 2];
    float a3 = d_a[b * 256 + colb + 3];
#pragma unroll
    for (int i = 0; i < 4; i++) {
        int m = m0 + ty * 4 + i;
        uint32_t h0 = (uint32_t)__bfloat16_as_ushort(__float2bfloat16(acc[i][0] * a0));
        uint32_t h1 = (uint32_t)__bfloat16_as_ushort(__float2bfloat16(acc[i][1] * a1));
        uint32_t h2 = (uint32_t)__bfloat16_as_ushort(__float2bfloat16(acc[i][2] * a2));
        uint32_t h3 = (uint32_t)__bfloat16_as_ushort(__float2bfloat16(acc[i][3] * a3));
        uint2 v; v.x = h0 | (h1 << 16); v.y = h2 | (h3 << 16);
        *(uint2*)&d_F1[(size_t)(b * 256 + m) * 256 + colb] = v;
    }
}

// ---------------- 9) HMMA final GEMM, 2-stage: out = F@x + g + skip ----------------
__global__ void __launch_bounds__(256, 2) fgemm_kernel(const float* __restrict__ x,
                                                       float* __restrict__ out) {
    extern __shared__ char sm[];
    int b = blockIdx.z;
    int m0 = blockIdx.x * 128;
    int n0 = blockIdx.y * 128;
    int tid = threadIdx.x, wid = tid >> 5, l = tid & 31;
    int wr = wid >> 2, wc = wid & 3;
    uint32_t sb = smem_u32(sm);

    const __nv_bfloat16* A1 = d_F1 + b * 65536;
    const __nv_bfloat16* B1 = d_b1 + (size_t)b * CHW;

    float acc[4][4][4] = {};
    int frag_row = ((l >> 3) & 1) * 8 + (l & 7);
    int koff = (l >> 4) * 8;

    auto issue = [&](int ch, int st) {
        int k0 = ch * 64;
#pragma unroll
        for (int it = 0; it < 8; it++) {
            int s = tid + it * 256;          // 0..2047
            if (s < 1024) {                  // A
                int r = s >> 3;
                int c = s & 7;
                uint32_t dst = sb + st * 32768 + SWA((uint32_t)(r * 128 + c * 16));
                cp16(dst, A1 + (m0 + r) * 256 + k0 + c * 8);
            } else {                         // B
                int v2 = s & 1023;
                int kr = v2 >> 4;
                int c = v2 & 15;
                uint32_t dst = sb + st * 32768 + 16384 + SWB((uint32_t)(kr * 256 + c * 16));
                cp16(dst, B1 + (size_t)(k0 + kr) * HWN + n0 + c * 8);
            }
        }
        CP_COMMIT();
    };

    issue(0, 0);
    for (int ch = 0; ch < 4; ch++) {
        int st = ch & 1;
        if (ch + 1 < 4) { issue(ch + 1, st ^ 1); CP_WAIT_1(); }
        else            { CP_WAIT_0(); }
        __syncthreads();
        uint32_t stb = sb + st * 32768;
#pragma unroll
        for (int ks = 0; ks < 4; ks++) {
            int kb = (ks * 16 + koff) * 2;
            uint32_t a[4][4], bf[2][4];
#pragma unroll
            for (int g = 0; g < 2; g++) {
                uint32_t off = (uint32_t)((ks * 16 + frag_row) * 256
                                          + (wc * 32 + g * 16 + koff) * 2);
                ldm_x4_t(bf[g], stb + 16384 + SWB(off));
            }
#pragma unroll
            for (int mt = 0; mt < 4; mt++) {
                uint32_t off = (uint32_t)((wr * 64 + mt * 16 + frag_row) * 128 + kb);
                ldm_x4(a[mt], stb + SWA(off));
            }
#pragma unroll
            for (int mt = 0; mt < 4; mt++)
#pragma unroll
                for (int nt = 0; nt < 4; nt++) {
                    int g = nt >> 1, p = nt & 1;
                    mma_bf16(acc[mt][nt], a[mt], bf[g][p*2], bf[g][p*2+1]);
                }
        }
        __syncthreads();
    }
    const float* xb = x + (size_t)b * CHW;
    float* ob = out + (size_t)b * CHW;
#pragma unroll
    for (int mt = 0; mt < 4; mt++) {
        int row = m0 + wr * 64 + mt * 16 + (l >> 2);
        float g0 = d_g[b * 256 + row];
        float g1 = d_g[b * 256 + row + 8];
#pragma unroll
        for (int nt = 0; nt < 4; nt++) {
            int col = n0 + wc * 32 + nt * 8 + (l & 3) * 2;
            float2 s0 = *(const float2*)&xb[(size_t)row * HWN + col];
            float2 s1 = *(const float2*)&xb[(size_t)(row + 8) * HWN + col];
            float2 v0, v1;
            v0.x = acc[mt][nt][0] + g0 + s0.x;
            v0.y = acc[mt][nt][1] + g0 + s0.y;
            v1.x = acc[mt][nt][2] + g1 + s1.x;
            v1.y = acc[mt][nt][3] + g1 + s1.y;
            *(float2*)&ob[(size_t)row * HWN + col] = v0;
            *(float2*)&ob[(size_t)(row + 8) * HWN + col] = v1;
        }
    }
}

// ---------------- launch ----------------
extern "C" void kernel_launch(void* const* d_in, const int* in_sizes, int n_in,
                              void* d_out, int out_size) {
    const float* x    = (const float*)d_in[0];
    const float* gnw  = (const float*)d_in[1];
    const float* gnb  = (const float*)d_in[2];
    const float* qkvw = (const float*)d_in[3];
    const float* qkvb = (const float*)d_in[4];
    const float* outw = (const float*)d_in[5];
    const float* outb = (const float*)d_in[6];
    float* out = (float*)d_out;

    cudaFuncSetAttribute(gram_mma_kernel, cudaFuncAttributeMaxDynamicSharedMemorySize, 98304);
    cudaFuncSetAttribute(fgemm_kernel,    cudaFuncAttributeMaxDynamicSharedMemorySize, 65536);

    convstats_kernel<<<BATCH * CC, 256>>>(x);
    prep_kernel<<<7, 128>>>(qkvw, qkvb, gnb, gnw);
    gram_mma_kernel<<<dim3(7, GS, BATCH), 256, 98304>>>();
    sumG_kernel<<<1792, 256>>>();
    combineG_kernel<<<1024, 256>>>();
    headscores_kernel<<<dim3(64, BATCH), 256>>>();
    softmax_t_kernel<<<BATCH, 512>>>(gnw, outw, outb);
    egemm_kernel<<<dim3(4, 4, BATCH), 256>>>(outw);
    fgemm_kernel<<<dim3(2, HWN / 128, BATCH), 256, 65536>>>(x, out);
}

// round 13
// speedup vs baseline: 1.2967x; 1.1772x over previous
#include <cuda_runtime.h>
#include <cuda_bf16.h>
#include <math.h>
#include <stdint.h>

#define HWN   16384
#define CC    256
#define BATCH 4
#define CHW   (CC*HWN)
#define GS    24        // gram split-K (3 jobs x 24 splits x 4 batch = 288 CTAs ~ 1 wave @2/SM)

// ---------------- scratch (static __device__, no allocations) ----------------
__device__ __align__(16) float d_Sx[BATCH*CC];
__device__ __align__(16) float d_Sxx[BATCH*CC];
__device__ __align__(16) float d_m[BATCH*CC];
__device__ __align__(16) float d_a[BATCH*CC];
__device__ __align__(16) float d_wa[BATCH*CC];
__device__ __align__(16) float d_rp[BATCH*CC];
__device__ __align__(16) float d_Wq[CC*CC];
__device__ __align__(16) float d_Wk[CC*CC];
__device__ __align__(16) float d_Wv[CC*CC];
__device__ __align__(16) float d_btq[CC];
__device__ __align__(16) float d_btk[CC];
__device__ __align__(16) float d_btv[CC];
__device__ __align__(16) __nv_bfloat16 d_b1[BATCH*CHW];   // 32 MB
__device__ __align__(16) float d_Gp[3*GS*BATCH*128*128];  // per-split tile partials (P jobs only)
__device__ __align__(16) float d_Gs[3*BATCH*128*128];     // split-summed tiles
__device__ __align__(16) float d_G[BATCH*CC*CC];
__device__ __align__(16) float d_sc[BATCH*64*16];
__device__ __align__(16) float d_T[BATCH*CC*CC];
__device__ __align__(16) __nv_bfloat16 d_F1[BATCH*CC*CC];
__device__ __align__(16) float d_g[BATCH*CC];

// ---------------- mma / ldmatrix / cp.async helpers (baseline PTX, sm_80+) ----------------
__device__ __forceinline__ uint32_t smem_u32(const void* p) {
    uint32_t a;
    asm("{ .reg .u64 t; cvta.to.shared.u64 t, %1; cvt.u32.u64 %0, t; }" : "=r"(a) : "l"(p));
    return a;
}
__device__ __forceinline__ void ldm_x4(uint32_t* r, uint32_t addr) {
    asm volatile("ldmatrix.sync.aligned.m8n8.x4.shared.b16 {%0,%1,%2,%3}, [%4];"
                 : "=r"(r[0]), "=r"(r[1]), "=r"(r[2]), "=r"(r[3]) : "r"(addr));
}
__device__ __forceinline__ void ldm_x4_t(uint32_t* r, uint32_t addr) {
    asm volatile("ldmatrix.sync.aligned.m8n8.x4.trans.shared.b16 {%0,%1,%2,%3}, [%4];"
                 : "=r"(r[0]), "=r"(r[1]), "=r"(r[2]), "=r"(r[3]) : "r"(addr));
}
__device__ __forceinline__ void mma_bf16(float* c, const uint32_t* a,
                                         uint32_t b0, uint32_t b1) {
    asm volatile("mma.sync.aligned.m16n8k16.row.col.f32.bf16.bf16.f32 "
                 "{%0,%1,%2,%3}, {%4,%5,%6,%7}, {%8,%9}, {%0,%1,%2,%3};"
                 : "+f"(c[0]), "+f"(c[1]), "+f"(c[2]), "+f"(c[3])
                 : "r"(a[0]), "r"(a[1]), "r"(a[2]), "r"(a[3]), "r"(b0), "r"(b1));
}
__device__ __forceinline__ void cp16(uint32_t dst, const void* src) {
    asm volatile("cp.async.cg.shared.global [%0], [%1], 16;" :: "r"(dst), "l"(src) : "memory");
}
#define CP_COMMIT()  asm volatile("cp.async.commit_group;" ::: "memory")
#define CP_WAIT_2()  asm volatile("cp.async.wait_group 2;" ::: "memory")
#define CP_WAIT_1()  asm volatile("cp.async.wait_group 1;" ::: "memory")
#define CP_WAIT_0()  asm volatile("cp.async.wait_group 0;" ::: "memory")

#define SWA(o) ((o) ^ (((o) >> 3) & 0x70))
#define SWB(o) ((o) ^ ((((o) >> 8) & 7) << 4))

// ---------------- 1) fused convert + stats (single bf16 output) ----------------
__global__ void convstats_kernel(const float* __restrict__ x) {
    int bc = blockIdx.x;
    const float4* p = (const float4*)(x + (size_t)bc * HWN);
    uint2* o1 = (uint2*)(d_b1 + (size_t)bc * HWN);
    float s = 0.f, s2 = 0.f;
    for (int i = threadIdx.x; i < HWN/4; i += 256) {
        float4 v = p[i];
        float in[4] = {v.x, v.y, v.z, v.w};
        uint32_t hh[4];
#pragma unroll
        for (int j = 0; j < 4; j++) {
            s  += in[j];
            s2 += in[j] * in[j];
            hh[j] = (uint32_t)__bfloat16_as_ushort(__float2bfloat16(in[j]));
        }
        uint2 ph; ph.x = hh[0] | (hh[1] << 16); ph.y = hh[2] | (hh[3] << 16);
        o1[i] = ph;
    }
    for (int o = 16; o; o >>= 1) {
        s  += __shfl_down_sync(0xffffffffu, s, o);
        s2 += __shfl_down_sync(0xffffffffu, s2, o);
    }
    __shared__ float sh[8][2];
    int w = threadIdx.x >> 5, l = threadIdx.x & 31;
    if (l == 0) { sh[w][0] = s; sh[w][1] = s2; }
    __syncthreads();
    if (threadIdx.x == 0) {
        float S = 0.f, S2 = 0.f;
        for (int i = 0; i < 8; i++) { S += sh[i][0]; S2 += sh[i][1]; }
        d_Sx[bc] = S; d_Sxx[bc] = S2;
    }
}

// ---------------- 2) prep = pack(blocks 0-5) + groupstats(block 6) ----------------
__global__ void prep_kernel(const float* __restrict__ qkvw,
                            const float* __restrict__ qkvb,
                            const float* __restrict__ gnb,
                            const float* __restrict__ gnw) {
    if (blockIdx.x < 6) {
        int rid = blockIdx.x * 128 + threadIdx.x;     // 0..767
        int sel = rid / 256;
        int p   = rid % 256;
        int h = p >> 2, dd = p & 3;
        int src = h * 12 + sel * 4 + dd;
        const float* wrow = qkvw + src * 256;
        float* dst = (sel == 0 ? d_Wq : (sel == 1 ? d_Wk : d_Wv)) + p * 256;
        float dot = 0.f;
        for (int c = 0; c < 256; c++) {
            float w = wrow[c];
            dst[c] = w;
            dot += w * gnb[c];
        }
        float bt = qkvb[src] + dot;
        if (sel == 0) d_btq[p] = bt; else if (sel == 1) d_btk[p] = bt; else d_btv[p] = bt;
    } else {
        int t = threadIdx.x;             // 0..127 = (b,g)
        int b = t >> 5, g = t & 31;
        float s = 0.f, s2 = 0.f;
        for (int c8 = 0; c8 < 8; c8++) {
            int idx = b * 256 + g * 8 + c8;
            s += d_Sx[idx]; s2 += d_Sxx[idx];
        }
        const float n = 8.f * (float)HWN;
        float mean = s / n;
        float var  = (s2 - n * mean * mean) / (n - 1.f);
        float a = rsqrtf(var + 1e-5f);
        for (int c8 = 0; c8 < 8; c8++) {
            int c = g * 8 + c8;
            int idx = b * 256 + c;
            d_m[idx] = mean;
            d_a[idx] = a;
            float wa = gnw[c] * a;
            d_wa[idx] = wa;
            d_rp[idx] = wa * (d_Sx[idx] - (float)HWN * mean);
        }
    }
}

// ---------------- 3) HMMA Gram tiles: 3 symmetric jobs (single bf16), 3-stage pipeline ----------------
// jid 0..2: P = b1_i b1_j^T, (ti,tj) in {(0,0),(0,1),(1,1)}; (1,0) by symmetry in combine.
// GS=24 splits over 256 chunks: splits 0-15 get 11, 16-23 get 10.
__global__ void __launch_bounds__(256, 2) gram_mma_kernel() {
    extern __shared__ char sm[];
    int b = blockIdx.z, split = blockIdx.y, jid = blockIdx.x;
    int ti = (jid == 2) ? 1 : 0;
    int tj = (jid == 0) ? 0 : 1;
    int nch = 10 + (split < 16 ? 1 : 0);
    int ch0 = split * 10 + (split < 16 ? split : 16);
    int tid = threadIdx.x, wid = tid >> 5, l = tid & 31;
    int wr = wid >> 2, wc = wid & 3;
    uint32_t sb = smem_u32(sm);

    const __nv_bfloat16* Ap = d_b1 + (size_t)b * CHW + (size_t)(ti * 128) * HWN;
    const __nv_bfloat16* Bp = d_b1 + (size_t)b * CHW + (size_t)(tj * 128) * HWN;

    float acc[4][4][4] = {};
    int frag_row = ((l >> 3) & 1) * 8 + (l & 7);
    int koff = (l >> 4) * 8;

    auto issue = [&](int ch, int st) {
        int k0 = (ch0 + ch) * 64;
#pragma unroll
        for (int it = 0; it < 8; it++) {
            int s = tid + it * 256;          // 0..2047
            int buf = s >> 10;
            int r = (s >> 3) & 127;
            int c = s & 7;
            const __nv_bfloat16* src = buf ? Bp : Ap;
            uint32_t dst = sb + st * 32768 + buf * 16384
                         + SWA((uint32_t)(r * 128 + c * 16));
            cp16(dst, src + (size_t)r * HWN + k0 + c * 8);
        }
        CP_COMMIT();
    };

    issue(0, 0);
    issue(1, 1);
    for (int ch = 0; ch < nch; ch++) {
        int st = ch % 3;
        if (ch + 2 < nch)      { issue(ch + 2, (ch + 2) % 3); CP_WAIT_2(); }
        else if (ch + 1 < nch) { CP_WAIT_1(); }
        else                   { CP_WAIT_0(); }
        __syncthreads();
        uint32_t stb = sb + st * 32768;
#pragma unroll
        for (int ks = 0; ks < 4; ks++) {
            int kb = (ks * 16 + koff) * 2;
            uint32_t a[4][4], bf[2][4];
#pragma unroll
            for (int g = 0; g < 2; g++) {
                uint32_t off = (uint32_t)((wc * 32 + g * 16 + frag_row) * 128 + kb);
                ldm_x4(bf[g], stb + 16384 + SWA(off));
            }
#pragma unroll
            for (int mt = 0; mt < 4; mt++) {
                uint32_t off = (uint32_t)((wr * 64 + mt * 16 + frag_row) * 128 + kb);
                ldm_x4(a[mt], stb + SWA(off));
            }
#pragma unroll
            for (int mt = 0; mt < 4; mt++)
#pragma unroll
                for (int nt = 0; nt < 4; nt++) {
                    int g = nt >> 1, p = nt & 1;
                    mma_bf16(acc[mt][nt], a[mt], bf[g][p], bf[g][p + 2]);
                }
        }
        __syncthreads();
    }
    float* gp = d_Gp + ((size_t)((jid * GS + split) * BATCH + b)) * 16384;
#pragma unroll
    for (int mt = 0; mt < 4; mt++)
#pragma unroll
        for (int nt = 0; nt < 4; nt++) {
            int row = wr * 64 + mt * 16 + (l >> 2);
            int col = wc * 32 + nt * 8 + (l & 3) * 2;
            float2 v0; v0.x = acc[mt][nt][0]; v0.y = acc[mt][nt][1];
            float2 v1; v1.x = acc[mt][nt][2]; v1.y = acc[mt][nt][3];
            *(float2*)&gp[row * 128 + col] = v0;
            *(float2*)&gp[(row + 8) * 128 + col] = v1;
        }
}

// ---------------- 4) sum over splits (coalesced) ----------------
__global__ void sumG_kernel() {
    int o = blockIdx.x * 256 + threadIdx.x;     // < 3*4*16384 = 196608
    int j = o >> 16;                            // job
    int rb = o & 65535;                         // b*16384 + e
    size_t base = (size_t)j * GS * BATCH * 16384 + rb;
    float s = 0.f;
#pragma unroll
    for (int sp = 0; sp < GS; sp++) s += d_Gp[base + (size_t)sp * BATCH * 16384];
    d_Gs[o] = s;
}

// ---------------- 5) combine P (+symmetry) + GN corrections -> G' ----------------
__global__ void combineG_kernel() {
    int idx = blockIdx.x * 256 + threadIdx.x;   // < 4*65536
    int b = idx >> 16;
    int ij = idx & 65535;
    int i = ij >> 8, j = ij & 255;
    int hi = i >> 7, hj = j >> 7, il = i & 127, jl = j & 127;
    int pj = hi + hj;                            // 0,1,2
    int pe = (hi <= hj) ? (il * 128 + jl) : (jl * 128 + il);
    float sum = d_Gs[(pj * 4 + b) * 16384 + pe];
    int bi = b * 256 + i, bj = b * 256 + j;
    float g = d_wa[bi] * d_wa[bj] *
              (sum - d_m[bi] * d_Sx[bj] - d_m[bj] * d_Sx[bi] + (float)HWN * d_m[bi] * d_m[bj]);
    d_G[idx] = g;
}

// ---------------- 6) per-head scores: 4x4 block-diag of Wq G' Wk^T + corrections ----------------
__global__ void headscores_kernel() {
    int h = blockIdx.x, b = blockIdx.y;
    int tid = threadIdx.x;                        // 256
    __shared__ float wq_s[1024], wk_s[1024];
    __shared__ float red[8][24], fin[24];
    for (int i = tid; i < 1024; i += 256) {
        wq_s[i] = d_Wq[h * 1024 + i];
        wk_s[i] = d_Wk[h * 1024 + i];
    }
    __syncthreads();
    int c = tid;
    float v1[4] = {};
    const float* Gb = d_G + b * 65536 + c;
#pragma unroll 16
    for (int p = 0; p < 256; p++) {
        float g = Gb[p * 256];
        v1[0] += wq_s[p] * g;
        v1[1] += wq_s[256 + p] * g;
        v1[2] += wq_s[512 + p] * g;
        v1[3] += wq_s[768 + p] * g;
    }
    float rp = d_rp[b * 256 + c];
    float part[24];
#pragma unroll
    for (int d = 0; d < 4; d++)
#pragma unroll
        for (int e = 0; e < 4; e++)
            part[d * 4 + e] = v1[d] * wk_s[e * 256 + c];
#pragma unroll
    for (int d = 0; d < 4; d++) part[16 + d] = wq_s[d * 256 + c] * rp;
#pragma unroll
    for (int e = 0; e < 4; e++) part[20 + e] = wk_s[e * 256 + c] * rp;
#pragma unroll
    for (int k = 0; k < 24; k++)
        for (int o = 16; o; o >>= 1)
            part[k] += __shfl_down_sync(0xffffffffu, part[k], o);
    int wd = tid >> 5, ln = tid & 31;
    if (ln == 0)
#pragma unroll
        for (int k = 0; k < 24; k++) red[wd][k] = part[k];
    __syncthreads();
    if (tid < 24) {
        float s = 0.f;
        for (int w = 0; w < 8; w++) s += red[w][tid];
        fin[tid] = s;
    }
    __syncthreads();
    if (tid < 16) {
        int d = tid >> 2, e = tid & 3;
        float s = fin[tid]
                + fin[16 + d] * d_btk[h * 4 + e]
                + d_btq[h * 4 + d] * fin[20 + e]
                + (float)HWN * d_btq[h * 4 + d] * d_btk[h * 4 + e];
        d_sc[(b * 64 + h) * 16 + tid] = 0.5f * s;
    }
}

// ---------------- 7) softmax + T + u + g base ----------------
__global__ void softmax_t_kernel(const float* __restrict__ gnw,
                                 const float* __restrict__ outw,
                                 const float* __restrict__ outb) {
    int b = blockIdx.x;
    int tid = threadIdx.x;                 // 512
    __shared__ float Ssh[64][16];
    __shared__ float amsh[256], tvsh[256], ush[256], tmush[256];
    {
        int w = tid >> 5;                  // pair 0..15
        int l = tid & 31;
        float v0 = d_sc[((b * 64 + l) << 4) + w];
        float v1 = d_sc[((b * 64 + l + 32) << 4) + w];
        float mx = fmaxf(v0, v1);
        for (int o = 16; o; o >>= 1) mx = fmaxf(mx, __shfl_xor_sync(0xffffffffu, mx, o));
        float e0 = expf(v0 - mx), e1 = expf(v1 - mx);
        float s = e0 + e1;
        for (int o = 16; o; o >>= 1) s += __shfl_xor_sync(0xffffffffu, s, o);
        Ssh[l][w] = e0 / s;
        Ssh[l + 32][w] = e1 / s;
    }
    if (tid < 256) amsh[tid] = d_a[b * 256 + tid] * d_m[b * 256 + tid];
    __syncthreads();
    for (int e = tid; e < 65536; e += 512) {
        int p = e >> 8, c = e & 255;
        int h = p >> 2, dd = p & 3;
        const float* S = &Ssh[h][dd * 4];
        float s = S[0] * d_Wv[(h*4+0)*256 + c] + S[1] * d_Wv[(h*4+1)*256 + c]
                + S[2] * d_Wv[(h*4+2)*256 + c] + S[3] * d_Wv[(h*4+3)*256 + c];
        d_T[((size_t)b * 256 + p) * 256 + c] = gnw[c] * s;
    }
    if (tid < 256) {
        int h = tid >> 2, dd = tid & 3;
        float tv = 0.f;
        for (int e2 = 0; e2 < 4; e2++) tv += Ssh[h][dd * 4 + e2] * d_btv[h * 4 + e2];
        tvsh[tid] = tv;
    }
    __syncthreads();
    {
        int p = tid >> 1, half = tid & 1;
        const float* Trow = d_T + ((size_t)b * 256 + p) * 256 + half * 128;
        const float* am = amsh + half * 128;
        float u = 0.f;
        for (int c = 0; c < 128; c++) u += Trow[c] * am[c];
        u += __shfl_down_sync(0xffffffffu, u, 1);
        if (!half) ush[p] = u;
    }
    __syncthreads();
    if (tid < 256) tmush[tid] = tvsh[tid] - ush[tid];
    __syncthreads();
    if (tid < 256) {
        float g = outb[tid];
        const float* ow = outw + tid * 256;
        for (int p = 0; p < 256; p++) g += ow[p] * tmush[p];
        d_g[b * 256 + tid] = g;
    }
}

// ---------------- 8) E-GEMM: F1 = bf16( (out_w @ T) * diag(a) ) ----------------
__global__ void egemm_kernel(const float* __restrict__ outw) {
    int b = blockIdx.z;
    const float* A = outw;
    const float* B = d_T + b * 65536;

    __shared__ float As[16][64];
    __shared__ float Bs[16][64];
    int m0 = blockIdx.x * 64, n0 = blockIdx.y * 64;
    int tid = threadIdx.x;
    int tx = tid & 15, ty = tid >> 4;
    int ar = tid >> 2, asg = tid & 3;
    int br = tid >> 4, bc = tid & 15;
    float acc[4][4] = {};
    for (int k0 = 0; k0 < 256; k0 += 16) {
        float4 av = *(const float4*)&A[(m0 + ar) * 256 + k0 + asg * 4];
        As[asg*4+0][ar] = av.x; As[asg*4+1][ar] = av.y; As[asg*4+2][ar] = av.z; As[asg*4+3][ar] = av.w;
        float4 bv = *(const float4*)&B[(k0 + br) * 256 + n0 + bc * 4];
        *(float4*)&Bs[br][bc * 4] = bv;
        __syncthreads();
#pragma unroll
        for (int kk = 0; kk < 16; kk++) {
            float4 a4 = *(const float4*)&As[kk][ty * 4];
            float4 b4 = *(const float4*)&Bs[kk][tx * 4];
            float avv[4] = {a4.x, a4.y, a4.z, a4.w};
            float bvv[4] = {b4.x, b4.y, b4.z, b4.w};
#pragma unroll
            for (int i = 0; i < 4; i++)
#pragma unroll
                for (int j = 0; j < 4; j++)
                    acc[i][j] += avv[i] * bvv[j];
        }
        __syncthreads();
    }
    int colb = n0 + tx * 4;
    float a0 = d_a[b * 256 + colb + 0];
    float a1 = d_a[b * 256 + colb + 1];
    float a2 = d_a[b * 256 + colb + 2];
    float a3 = d_a[b * 256 + colb + 3];
#pragma unroll
    for (int i = 0; i < 4; i++) {
        int m = m0 + ty * 4 + i;
        uint32_t h0 = (uint32_t)__bfloat16_as_ushort(__float2bfloat16(acc[i][0] * a0));
        uint32_t h1 = (uint32_t)__bfloat16_as_ushort(__float2bfloat16(acc[i][1] * a1));
        uint32_t h2 = (uint32_t)__bfloat16_as_ushort(__float2bfloat16(acc[i][2] * a2));
        uint32_t h3 = (uint32_t)__bfloat16_as_ushort(__float2bfloat16(acc[i][3] * a3));
        uint2 v; v.x = h0 | (h1 << 16); v.y = h2 | (h3 << 16);
        *(uint2*)&d_F1[(size_t)(b * 256 + m) * 256 + colb] = v;
    }
}

// ---------------- 9) HMMA final GEMM, 2-stage: out = F@x + g + skip ----------------
__global__ void __launch_bounds__(256, 2) fgemm_kernel(const float* __restrict__ x,
                                                       float* __restrict__ out) {
    extern __shared__ char sm[];
    int b = blockIdx.z;
    int m0 = blockIdx.x * 128;
    int n0 = blockIdx.y * 128;
    int tid = threadIdx.x, wid = tid >> 5, l = tid & 31;
    int wr = wid >> 2, wc = wid & 3;
    uint32_t sb = smem_u32(sm);

    const __nv_bfloat16* A1 = d_F1 + b * 65536;
    const __nv_bfloat16* B1 = d_b1 + (size_t)b * CHW;

    float acc[4][4][4] = {};
    int frag_row = ((l >> 3) & 1) * 8 + (l & 7);
    int koff = (l >> 4) * 8;

    auto issue = [&](int ch, int st) {
        int k0 = ch * 64;
#pragma unroll
        for (int it = 0; it < 8; it++) {
            int s = tid + it * 256;          // 0..2047
            if (s < 1024) {                  // A
                int r = s >> 3;
                int c = s & 7;
                uint32_t dst = sb + st * 32768 + SWA((uint32_t)(r * 128 + c * 16));
                cp16(dst, A1 + (m0 + r) * 256 + k0 + c * 8);
            } else {                         // B
                int v2 = s & 1023;
                int kr = v2 >> 4;
                int c = v2 & 15;
                uint32_t dst = sb + st * 32768 + 16384 + SWB((uint32_t)(kr * 256 + c * 16));
                cp16(dst, B1 + (size_t)(k0 + kr) * HWN + n0 + c * 8);
            }
        }
        CP_COMMIT();
    };

    issue(0, 0);
    for (int ch = 0; ch < 4; ch++) {
        int st = ch & 1;
        if (ch + 1 < 4) { issue(ch + 1, st ^ 1); CP_WAIT_1(); }
        else            { CP_WAIT_0(); }
        __syncthreads();
        uint32_t stb = sb + st * 32768;
#pragma unroll
        for (int ks = 0; ks < 4; ks++) {
            int kb = (ks * 16 + koff) * 2;
            uint32_t a[4][4], bf[2][4];
#pragma unroll
            for (int g = 0; g < 2; g++) {
                uint32_t off = (uint32_t)((ks * 16 + frag_row) * 256
                                          + (wc * 32 + g * 16 + koff) * 2);
                ldm_x4_t(bf[g], stb + 16384 + SWB(off));
            }
#pragma unroll
            for (int mt = 0; mt < 4; mt++) {
                uint32_t off = (uint32_t)((wr * 64 + mt * 16 + frag_row) * 128 + kb);
                ldm_x4(a[mt], stb + SWA(off));
            }
#pragma unroll
            for (int mt = 0; mt < 4; mt++)
#pragma unroll
                for (int nt = 0; nt < 4; nt++) {
                    int g = nt >> 1, p = nt & 1;
                    mma_bf16(acc[mt][nt], a[mt], bf[g][p*2], bf[g][p*2+1]);
                }
        }
        __syncthreads();
    }
    const float* xb = x + (size_t)b * CHW;
    float* ob = out + (size_t)b * CHW;
#pragma unroll
    for (int mt = 0; mt < 4; mt++) {
        int row = m0 + wr * 64 + mt * 16 + (l >> 2);
        float g0 = d_g[b * 256 + row];
        float g1 = d_g[b * 256 + row + 8];
#pragma unroll
        for (int nt = 0; nt < 4; nt++) {
            int col = n0 + wc * 32 + nt * 8 + (l & 3) * 2;
            float2 s0 = *(const float2*)&xb[(size_t)row * HWN + col];
            float2 s1 = *(const float2*)&xb[(size_t)(row + 8) * HWN + col];
            float2 v0, v1;
            v0.x = acc[mt][nt][0] + g0 + s0.x;
            v0.y = acc[mt][nt][1] + g0 + s0.y;
            v1.x = acc[mt][nt][2] + g1 + s1.x;
            v1.y = acc[mt][nt][3] + g1 + s1.y;
            *(float2*)&ob[(size_t)row * HWN + col] = v0;
            *(float2*)&ob[(size_t)(row + 8) * HWN + col] = v1;
        }
    }
}

// ---------------- launch ----------------
extern "C" void kernel_launch(void* const* d_in, const int* in_sizes, int n_in,
                              void* d_out, int out_size) {
    const float* x    = (const float*)d_in[0];
    const float* gnw  = (const float*)d_in[1];
    const float* gnb  = (const float*)d_in[2];
    const float* qkvw = (const float*)d_in[3];
    const float* qkvb = (const float*)d_in[4];
    const float* outw = (const float*)d_in[5];
    const float* outb = (const float*)d_in[6];
    float* out = (float*)d_out;

    cudaFuncSetAttribute(gram_mma_kernel, cudaFuncAttributeMaxDynamicSharedMemorySize, 98304);
    cudaFuncSetAttribute(fgemm_kernel,    cudaFuncAttributeMaxDynamicSharedMemorySize, 65536);

    convstats_kernel<<<BATCH * CC, 256>>>(x);
    prep_kernel<<<7, 128>>>(qkvw, qkvb, gnb, gnw);
    gram_mma_kernel<<<dim3(3, GS, BATCH), 256, 98304>>>();
    sumG_kernel<<<768, 256>>>();
    combineG_kernel<<<1024, 256>>>();
    headscores_kernel<<<dim3(64, BATCH), 256>>>();
    softmax_t_kernel<<<BATCH, 512>>>(gnw, outw, outb);
    egemm_kernel<<<dim3(4, 4, BATCH), 256>>>(outw);
    fgemm_kernel<<<dim3(2, HWN / 128, BATCH), 256, 65536>>>(x, out);
}